// round 14
// baseline (speedup 1.0000x reference)
#include <cuda_runtime.h>
#include <cuda_bf16.h>
#include <cstdint>

// EdgeConvE: B=4, V=1024, C=64, E=16, K=32, OUT=128, NODES=4096, EDGES=131072
// src = repeat(arange(4096), 32) (structural) => segment n = edges [n*32,(n+1)*32)
// dst & 1023 = local neighbor (block-diagonal graphs).
//
// Algebra: feat@W = x_s@(W1-W2) + x_d@W2 + e@W3
//   A[n] = x_n@(W1-W2)+b ; C[n] = x_n@W2
//   out[n][j] = max(0, A[n][j] + max_k( C[dst_k][j] + e_k . W3[:,j] ))
//
// PDL: edge kernel launches while node_tables runs; input-only prologue
// (dst, E cp.async, W3) overlaps; gridDependencySynchronize() guards the
// C-table cp.async staging (kernel-1 output).
// ALL gathers are cp.async: the inner loop has no global loads at all.

#define NODES 4096
#define VDIM  1024
#define CDIM  64
#define EDIM  16
#define KNBR  32
#define OUTD  128
#define EPAD  20     // E smem row stride in floats (16B-aligned chunks)

__device__ float g_A[NODES * OUTD];
__device__ float g_C[NODES * OUTD];

// ---------------- f32x2 helpers ----------------
__device__ __forceinline__ uint64_t pack_f32x2(float lo, float hi) {
    uint64_t r;
    asm("mov.b64 %0, {%1, %2};" : "=l"(r) : "f"(lo), "f"(hi));
    return r;
}
__device__ __forceinline__ void unpack_f32x2(float& lo, float& hi, uint64_t v) {
    asm("mov.b64 {%0, %1}, %2;" : "=f"(lo), "=f"(hi) : "l"(v));
}
__device__ __forceinline__ uint64_t fma_f32x2(uint64_t a, uint64_t b, uint64_t c) {
    uint64_t d;
    asm("fma.rn.f32x2 %0, %1, %2, %3;" : "=l"(d) : "l"(a), "l"(b), "l"(c));
    return d;
}
__device__ __forceinline__ void lds_v2_u64(uint64_t& a, uint64_t& b, uint32_t addr) {
    asm("ld.shared.v2.u64 {%0, %1}, [%2];" : "=l"(a), "=l"(b) : "r"(addr));
}
__device__ __forceinline__ uint64_t lds_u64(uint32_t addr) {
    uint64_t a;
    asm("ld.shared.u64 %0, [%1];" : "=l"(a) : "r"(addr));
    return a;
}
__device__ __forceinline__ uint32_t smem_u32(const void* p) {
    return (uint32_t)__cvta_generic_to_shared(p);
}
__device__ __forceinline__ void cp_async16(uint32_t s, const void* g) {
    asm volatile("cp.async.cg.shared.global [%0], [%1], 16;" :: "r"(s), "l"(g));
}

// ---------------------------------------------------------------------------
// Kernel 1: per-node linear tables (f32x2-packed over node pairs). grid 1024.
// Fires the dependent edge kernel at entry (PDL).
// ---------------------------------------------------------------------------
#define NT_NODES 4
__global__ void __launch_bounds__(128) node_tables_kernel(
    const float* __restrict__ x, const float* __restrict__ W,
    const float* __restrict__ bias)
{
    cudaTriggerProgrammaticLaunchCompletion();

    __shared__ float xs[CDIM][NT_NODES];
    const int j  = threadIdx.x;
    const int n0 = blockIdx.x * NT_NODES;

    for (int it = 0; it < NT_NODES * CDIM / 128; it++) {
        int idx = j + it * 128;
        xs[idx & 63][idx >> 6] = x[n0 * CDIM + idx];
    }
    __syncthreads();

    const float bj = bias[j];
    uint64_t accA[NT_NODES / 2], accC[NT_NODES / 2];
#pragma unroll
    for (int p = 0; p < NT_NODES / 2; p++) {
        accA[p] = pack_f32x2(bj, bj);
        accC[p] = pack_f32x2(0.0f, 0.0f);
    }
    const uint32_t xs_base = smem_u32(&xs[0][0]);

#pragma unroll 8
    for (int c = 0; c < CDIM; c++) {
        const float w1 = W[c * OUTD + j];
        const float w2 = W[(CDIM + c) * OUTD + j];
        const uint64_t wd2 = pack_f32x2(w1 - w2, w1 - w2);
        const uint64_t w22 = pack_f32x2(w2, w2);
        const uint32_t rowa = xs_base + c * (NT_NODES * 4);
#pragma unroll
        for (int p = 0; p < NT_NODES / 2; p++) {
            uint64_t xv2 = lds_u64(rowa + p * 8);
            accA[p] = fma_f32x2(xv2, wd2, accA[p]);
            accC[p] = fma_f32x2(xv2, w22, accC[p]);
        }
    }
#pragma unroll
    for (int p = 0; p < NT_NODES / 2; p++) {
        float a0, a1, c0, c1;
        unpack_f32x2(a0, a1, accA[p]);
        unpack_f32x2(c0, c1, accC[p]);
        g_A[(n0 + 2 * p) * OUTD + j]     = a0;
        g_A[(n0 + 2 * p + 1) * OUTD + j] = a1;
        g_C[(n0 + 2 * p) * OUTD + j]     = c0;
        g_C[(n0 + 2 * p + 1) * OUTD + j] = c1;
    }
}

// ---------------------------------------------------------------------------
// Kernel 2: one node per 64-thread block (grid 4096), PDL-guarded, ALL-ASYNC:
//   group 0      : E rows (32 x 64B)          -- input, overlaps kernel 1
//   groups 1..4  : C rows in 8-row chunks     -- after gridDependencySync
//   Inner loop: smem-only (LDS), zero global loads -> no long-scoreboard.
// ---------------------------------------------------------------------------
__global__ void __launch_bounds__(64) edge_max_kernel(
    const float* __restrict__ eattr,  // [4,1024,1024,16]
    const float* __restrict__ W,      // [144,128]
    const int*   __restrict__ dst,    // [131072]
    float*       __restrict__ out)    // [4096,128]
{
    const int n  = blockIdx.x;
    const int t  = threadIdx.x;       // 0..63
    const int j0 = t * 2;

    __shared__ int sd[KNBR];
    __shared__ __align__(16) float se[KNBR][EPAD];   // 2.5 KB
    __shared__ __align__(16) float sC[KNBR][OUTD];   // 16 KB

    if (t < KNBR) sd[t] = dst[n * KNBR + t];
    __syncthreads();

    // ---- group 0: E rows (input-only; overlaps kernel 1 under PDL) ----
#pragma unroll
    for (int half = 0; half < 2; half++) {
        const int c  = t + half * 64;
        const int ck = c >> 2;
        const int cq = c & 3;
        const int ui = sd[ck] & (VDIM - 1);
        cp_async16(smem_u32(&se[ck][cq * 4]),
                   eattr + ((size_t)n * VDIM + ui) * EDIM + cq * 4);
    }
    asm volatile("cp.async.commit_group;");

    // W3 t-pair columns for cols j0, j0+1 (input-only)
    uint64_t w3a[8], w3b[8];
#pragma unroll
    for (int p = 0; p < 8; p++) {
        w3a[p] = pack_f32x2(W[(2 * CDIM + 2 * p) * OUTD + j0],
                            W[(2 * CDIM + 2 * p + 1) * OUTD + j0]);
        w3b[p] = pack_f32x2(W[(2 * CDIM + 2 * p) * OUTD + j0 + 1],
                            W[(2 * CDIM + 2 * p + 1) * OUTD + j0 + 1]);
    }

    // ---- wait for kernel 1's g_A/g_C, then stage C rows (groups 1..4) ----
    cudaGridDependencySynchronize();

#pragma unroll
    for (int cc = 0; cc < 4; cc++) {
        // 8 rows x 512B = 256 x 16B chunks, 4 per thread
#pragma unroll
        for (int i = 0; i < 4; i++) {
            const int idx = t + i * 64;          // 0..255
            const int row = cc * 8 + (idx >> 5); // 8 rows, 32 chunks each
            const int q   = idx & 31;
            cp_async16(smem_u32(&sC[row][q * 4]),
                       g_C + (size_t)sd[row] * OUTD + q * 4);
        }
        asm volatile("cp.async.commit_group;");
    }

    const float2 av = *reinterpret_cast<const float2*>(g_A + n * OUTD + j0);

    const uint32_t se_base = smem_u32(&se[0][0]);
    const uint32_t sc_base = smem_u32(&sC[0][0]);
    float best0 = -1e30f, best1 = -1e30f;

#pragma unroll
    for (int kb = 0; kb < KNBR; kb += 8) {
        // wait until E + C-chunks(0..kb/8) have landed
        if (kb == 0)       asm volatile("cp.async.wait_group 3;");
        else if (kb == 8)  asm volatile("cp.async.wait_group 2;");
        else if (kb == 16) asm volatile("cp.async.wait_group 1;");
        else               asm volatile("cp.async.wait_group 0;");
        __syncthreads();

#pragma unroll
        for (int u = 0; u < 8; u++) {
            const int k = kb + u;
            const uint32_t row = se_base + k * (EPAD * 4);
            const uint64_t cvp = lds_u64(sc_base + (k * OUTD + j0) * 4); // (C0,C1)

            uint64_t e0, e1, e2, e3, e4, e5, e6, e7;
            lds_v2_u64(e0, e1, row);
            lds_v2_u64(e2, e3, row + 16);
            lds_v2_u64(e4, e5, row + 32);
            lds_v2_u64(e6, e7, row + 48);

            float cv0, cv1;
            unpack_f32x2(cv0, cv1, cvp);
            uint64_t a0 = pack_f32x2(cv0, 0.0f);
            uint64_t a1 = pack_f32x2(cv1, 0.0f);
            a0 = fma_f32x2(e0, w3a[0], a0);  a1 = fma_f32x2(e0, w3b[0], a1);
            a0 = fma_f32x2(e1, w3a[1], a0);  a1 = fma_f32x2(e1, w3b[1], a1);
            a0 = fma_f32x2(e2, w3a[2], a0);  a1 = fma_f32x2(e2, w3b[2], a1);
            a0 = fma_f32x2(e3, w3a[3], a0);  a1 = fma_f32x2(e3, w3b[3], a1);
            a0 = fma_f32x2(e4, w3a[4], a0);  a1 = fma_f32x2(e4, w3b[4], a1);
            a0 = fma_f32x2(e5, w3a[5], a0);  a1 = fma_f32x2(e5, w3b[5], a1);
            a0 = fma_f32x2(e6, w3a[6], a0);  a1 = fma_f32x2(e6, w3b[6], a1);
            a0 = fma_f32x2(e7, w3a[7], a0);  a1 = fma_f32x2(e7, w3b[7], a1);

            float lo0, hi0, lo1, hi1;
            unpack_f32x2(lo0, hi0, a0);
            unpack_f32x2(lo1, hi1, a1);
            best0 = fmaxf(best0, lo0 + hi0);
            best1 = fmaxf(best1, lo1 + hi1);
        }
    }

    float r0 = fmaxf(av.x + best0, 0.0f);
    float r1 = fmaxf(av.y + best1, 0.0f);
    *reinterpret_cast<float2*>(out + n * OUTD + j0) = make_float2(r0, r1);
}

// ---------------------------------------------------------------------------
// Inputs: 0 node_features [4,1024,64] f32 | 1 edge_attributes [4,1024,1024,16] f32
//         2 W [144,128] f32 | 3 b [128] f32 | 4 src i32 (unused) | 5 dst i32
// Output: f32 [4,1024,128]
// ---------------------------------------------------------------------------
extern "C" void kernel_launch(void* const* d_in, const int* in_sizes, int n_in,
                              void* d_out, int out_size)
{
    const float* x     = (const float*)d_in[0];
    const float* eattr = (const float*)d_in[1];
    const float* W     = (const float*)d_in[2];
    const float* bias  = (const float*)d_in[3];
    const int*   dst   = (const int*)d_in[5];
    float*       out   = (float*)d_out;

    node_tables_kernel<<<NODES / NT_NODES, 128>>>(x, W, bias);

    cudaLaunchConfig_t cfg = {};
    cfg.gridDim  = dim3(NODES);
    cfg.blockDim = dim3(64);
    cudaLaunchAttribute attrs[1];
    attrs[0].id = cudaLaunchAttributeProgrammaticStreamSerialization;
    attrs[0].val.programmaticStreamSerializationAllowed = 1;
    cfg.attrs = attrs;
    cfg.numAttrs = 1;
    cudaLaunchKernelEx(&cfg, edge_max_kernel, eattr, W, dst, out);
}

// round 16
// speedup vs baseline: 1.0094x; 1.0094x over previous
#include <cuda_runtime.h>
#include <cuda_bf16.h>
#include <cstdint>

// EdgeConvE: B=4, V=1024, C=64, E=16, K=32, OUT=128, NODES=4096, EDGES=131072
// src = repeat(arange(4096), 32) (structural) => segment n = edges [n*32,(n+1)*32)
// dst & 1023 = local neighbor (block-diagonal graphs).
//
// Algebra: feat@W = x_s@(W1-W2) + x_d@W2 + e@W3
//   A[n] = x_n@(W1-W2)+b ; C[n] = x_n@W2
//   out[n][j] = max(0, A[n][j] + max_k( C[dst_k][j] + e_k . W3[:,j] ))
//
// PDL + all-async staging + 2-deep C ring (8KB) + 56-reg cap.
// R15 fix: all smem-touching asm is volatile + "memory"-clobbered so LDS
// reads cannot be compiler-sunk past the ring refill (the R14 corruption).

#define NODES 4096
#define VDIM  1024
#define CDIM  64
#define EDIM  16
#define KNBR  32
#define OUTD  128
#define EPAD  20     // E smem row stride in floats (16B-aligned chunks)

__device__ float g_A[NODES * OUTD];
__device__ float g_C[NODES * OUTD];

// ---------------- f32x2 helpers ----------------
__device__ __forceinline__ uint64_t pack_f32x2(float lo, float hi) {
    uint64_t r;
    asm("mov.b64 %0, {%1, %2};" : "=l"(r) : "f"(lo), "f"(hi));
    return r;
}
__device__ __forceinline__ void unpack_f32x2(float& lo, float& hi, uint64_t v) {
    asm("mov.b64 {%0, %1}, %2;" : "=f"(lo), "=f"(hi) : "l"(v));
}
__device__ __forceinline__ uint64_t fma_f32x2(uint64_t a, uint64_t b, uint64_t c) {
    uint64_t d;
    asm("fma.rn.f32x2 %0, %1, %2, %3;" : "=l"(d) : "l"(a), "l"(b), "l"(c));
    return d;
}
// VOLATILE + memory clobber: these reads must not move across cp.async
// refills or barriers (ring-buffer reuse hazard).
__device__ __forceinline__ void lds_v2_u64(uint64_t& a, uint64_t& b, uint32_t addr) {
    asm volatile("ld.shared.v2.u64 {%0, %1}, [%2];"
                 : "=l"(a), "=l"(b) : "r"(addr) : "memory");
}
__device__ __forceinline__ uint64_t lds_u64(uint32_t addr) {
    uint64_t a;
    asm volatile("ld.shared.u64 %0, [%1];" : "=l"(a) : "r"(addr) : "memory");
    return a;
}
__device__ __forceinline__ uint32_t smem_u32(const void* p) {
    return (uint32_t)__cvta_generic_to_shared(p);
}
__device__ __forceinline__ void cp_async16(uint32_t s, const void* g) {
    asm volatile("cp.async.cg.shared.global [%0], [%1], 16;"
                 :: "r"(s), "l"(g) : "memory");
}

// ---------------------------------------------------------------------------
// Kernel 1: per-node linear tables (f32x2-packed over node pairs). grid 1024.
// Fires the dependent edge kernel at entry (PDL).
// ---------------------------------------------------------------------------
#define NT_NODES 4
__global__ void __launch_bounds__(128) node_tables_kernel(
    const float* __restrict__ x, const float* __restrict__ W,
    const float* __restrict__ bias)
{
    cudaTriggerProgrammaticLaunchCompletion();

    __shared__ float xs[CDIM][NT_NODES];
    const int j  = threadIdx.x;
    const int n0 = blockIdx.x * NT_NODES;

    for (int it = 0; it < NT_NODES * CDIM / 128; it++) {
        int idx = j + it * 128;
        xs[idx & 63][idx >> 6] = x[n0 * CDIM + idx];
    }
    __syncthreads();

    const float bj = bias[j];
    uint64_t accA[NT_NODES / 2], accC[NT_NODES / 2];
#pragma unroll
    for (int p = 0; p < NT_NODES / 2; p++) {
        accA[p] = pack_f32x2(bj, bj);
        accC[p] = pack_f32x2(0.0f, 0.0f);
    }
    const uint32_t xs_base = smem_u32(&xs[0][0]);

#pragma unroll 8
    for (int c = 0; c < CDIM; c++) {
        const float w1 = W[c * OUTD + j];
        const float w2 = W[(CDIM + c) * OUTD + j];
        const uint64_t wd2 = pack_f32x2(w1 - w2, w1 - w2);
        const uint64_t w22 = pack_f32x2(w2, w2);
        const uint32_t rowa = xs_base + c * (NT_NODES * 4);
#pragma unroll
        for (int p = 0; p < NT_NODES / 2; p++) {
            uint64_t xv2 = lds_u64(rowa + p * 8);
            accA[p] = fma_f32x2(xv2, wd2, accA[p]);
            accC[p] = fma_f32x2(xv2, w22, accC[p]);
        }
    }
#pragma unroll
    for (int p = 0; p < NT_NODES / 2; p++) {
        float a0, a1, c0, c1;
        unpack_f32x2(a0, a1, accA[p]);
        unpack_f32x2(c0, c1, accC[p]);
        g_A[(n0 + 2 * p) * OUTD + j]     = a0;
        g_A[(n0 + 2 * p + 1) * OUTD + j] = a1;
        g_C[(n0 + 2 * p) * OUTD + j]     = c0;
        g_C[(n0 + 2 * p + 1) * OUTD + j] = c1;
    }
}

// ---------------------------------------------------------------------------
// Kernel 2: one node per 64-thread block (grid 4096), PDL-guarded, all-async,
// C staged through a 2-deep 8-row ring (8 KB), regs capped at 56 via
// launch_bounds(64,18).
// ---------------------------------------------------------------------------
__global__ void __launch_bounds__(64, 18) edge_max_kernel(
    const float* __restrict__ eattr,  // [4,1024,1024,16]
    const float* __restrict__ W,      // [144,128]
    const int*   __restrict__ dst,    // [131072]
    float*       __restrict__ out)    // [4096,128]
{
    const int n  = blockIdx.x;
    const int t  = threadIdx.x;       // 0..63
    const int j0 = t * 2;

    __shared__ int sd[KNBR];
    __shared__ __align__(16) float se[KNBR][EPAD];    // 2.5 KB
    __shared__ __align__(16) float sC[2][8][OUTD];    // 8 KB ring

    if (t < KNBR) sd[t] = dst[n * KNBR + t];
    __syncthreads();

    // ---- group E: edge-attr rows (input-only; overlaps kernel 1 via PDL) --
#pragma unroll
    for (int half = 0; half < 2; half++) {
        const int c  = t + half * 64;
        const int ck = c >> 2;
        const int cq = c & 3;
        const int ui = sd[ck] & (VDIM - 1);
        cp_async16(smem_u32(&se[ck][cq * 4]),
                   eattr + ((size_t)n * VDIM + ui) * EDIM + cq * 4);
    }
    asm volatile("cp.async.commit_group;" ::: "memory");

    // W3 t-pair columns for cols j0, j0+1 (input-only)
    uint64_t w3a[8], w3b[8];
#pragma unroll
    for (int p = 0; p < 8; p++) {
        w3a[p] = pack_f32x2(W[(2 * CDIM + 2 * p) * OUTD + j0],
                            W[(2 * CDIM + 2 * p + 1) * OUTD + j0]);
        w3b[p] = pack_f32x2(W[(2 * CDIM + 2 * p) * OUTD + j0 + 1],
                            W[(2 * CDIM + 2 * p + 1) * OUTD + j0 + 1]);
    }

    // ---- wait for kernel 1, then prime the C ring with chunks 0 and 1 ----
    cudaGridDependencySynchronize();

#pragma unroll
    for (int cc = 0; cc < 2; cc++) {
#pragma unroll
        for (int i = 0; i < 4; i++) {
            const int idx = t + i * 64;
            const int r   = idx >> 5;            // 0..7
            const int q   = idx & 31;
            cp_async16(smem_u32(&sC[cc][r][q * 4]),
                       g_C + (size_t)sd[cc * 8 + r] * OUTD + q * 4);
        }
        asm volatile("cp.async.commit_group;" ::: "memory");
    }

    const float2 av = *reinterpret_cast<const float2*>(g_A + n * OUTD + j0);

    const uint32_t se_base = smem_u32(&se[0][0]);
    float best0 = -1e30f, best1 = -1e30f;

#pragma unroll
    for (int cc = 0; cc < 4; cc++) {
        // oldest pending groups (E and C[cc]) must have landed
        if (cc < 3) asm volatile("cp.async.wait_group 1;" ::: "memory");
        else        asm volatile("cp.async.wait_group 0;" ::: "memory");
        __syncthreads();

        const uint32_t sc_row = smem_u32(&sC[cc & 1][0][0]);
#pragma unroll
        for (int u = 0; u < 8; u++) {
            const int k = cc * 8 + u;
            const uint32_t row = se_base + k * (EPAD * 4);
            const uint64_t cvp = lds_u64(sc_row + (u * OUTD + j0) * 4);

            float cv0, cv1;
            unpack_f32x2(cv0, cv1, cvp);
            uint64_t a0 = pack_f32x2(cv0, 0.0f);
            uint64_t a1 = pack_f32x2(cv1, 0.0f);

            {   // e-row first half (peak 4 u64 live)
                uint64_t e0, e1, e2, e3;
                lds_v2_u64(e0, e1, row);
                lds_v2_u64(e2, e3, row + 16);
                a0 = fma_f32x2(e0, w3a[0], a0);  a1 = fma_f32x2(e0, w3b[0], a1);
                a0 = fma_f32x2(e1, w3a[1], a0);  a1 = fma_f32x2(e1, w3b[1], a1);
                a0 = fma_f32x2(e2, w3a[2], a0);  a1 = fma_f32x2(e2, w3b[2], a1);
                a0 = fma_f32x2(e3, w3a[3], a0);  a1 = fma_f32x2(e3, w3b[3], a1);
            }
            {   // second half
                uint64_t e4, e5, e6, e7;
                lds_v2_u64(e4, e5, row + 32);
                lds_v2_u64(e6, e7, row + 48);
                a0 = fma_f32x2(e4, w3a[4], a0);  a1 = fma_f32x2(e4, w3b[4], a1);
                a0 = fma_f32x2(e5, w3a[5], a0);  a1 = fma_f32x2(e5, w3b[5], a1);
                a0 = fma_f32x2(e6, w3a[6], a0);  a1 = fma_f32x2(e6, w3b[6], a1);
                a0 = fma_f32x2(e7, w3a[7], a0);  a1 = fma_f32x2(e7, w3b[7], a1);
            }

            float lo0, hi0, lo1, hi1;
            unpack_f32x2(lo0, hi0, a0);
            unpack_f32x2(lo1, hi1, a1);
            best0 = fmaxf(best0, lo0 + hi0);
            best1 = fmaxf(best1, lo1 + hi1);
        }

        // refill the consumed buffer with chunk cc+2
        if (cc < 2) {
            __syncthreads();   // all warps done reading sC[cc&1]
#pragma unroll
            for (int i = 0; i < 4; i++) {
                const int idx = t + i * 64;
                const int r   = idx >> 5;
                const int q   = idx & 31;
                cp_async16(smem_u32(&sC[cc & 1][r][q * 4]),
                           g_C + (size_t)sd[(cc + 2) * 8 + r] * OUTD + q * 4);
            }
            asm volatile("cp.async.commit_group;" ::: "memory");
        }
    }

    float r0 = fmaxf(av.x + best0, 0.0f);
    float r1 = fmaxf(av.y + best1, 0.0f);
    *reinterpret_cast<float2*>(out + n * OUTD + j0) = make_float2(r0, r1);
}

// ---------------------------------------------------------------------------
// Inputs: 0 node_features [4,1024,64] f32 | 1 edge_attributes [4,1024,1024,16] f32
//         2 W [144,128] f32 | 3 b [128] f32 | 4 src i32 (unused) | 5 dst i32
// Output: f32 [4,1024,128]
// ---------------------------------------------------------------------------
extern "C" void kernel_launch(void* const* d_in, const int* in_sizes, int n_in,
                              void* d_out, int out_size)
{
    const float* x     = (const float*)d_in[0];
    const float* eattr = (const float*)d_in[1];
    const float* W     = (const float*)d_in[2];
    const float* bias  = (const float*)d_in[3];
    const int*   dst   = (const int*)d_in[5];
    float*       out   = (float*)d_out;

    node_tables_kernel<<<NODES / NT_NODES, 128>>>(x, W, bias);

    cudaLaunchConfig_t cfg = {};
    cfg.gridDim  = dim3(NODES);
    cfg.blockDim = dim3(64);
    cudaLaunchAttribute attrs[1];
    attrs[0].id = cudaLaunchAttributeProgrammaticStreamSerialization;
    attrs[0].val.programmaticStreamSerializationAllowed = 1;
    cfg.attrs = attrs;
    cfg.numAttrs = 1;
    cudaLaunchKernelEx(&cfg, edge_max_kernel, eattr, W, dst, out);
}